// round 2
// baseline (speedup 1.0000x reference)
#include <cuda_runtime.h>
#include <math.h>

// Problem-fixed dimensions (from reference: N=50000, E=800000, 512->256->64)
#define NMAX   50000
#define K1     512
#define F1     256
#define F2     64

// ---------------- scratch (static device globals; no allocations) ----------
__device__ int   g_deg_out[NMAX];
__device__ int   g_deg_in [NMAX];
__device__ float g_nsrc[NMAX];
__device__ float g_ndst[NMAX];
__device__ float g_H1[(size_t)NMAX * F1];   // X@W1            (51.2 MB)
__device__ float g_A1[(size_t)NMAX * F1];   // scatter target / h1 (51.2 MB)
__device__ float g_H2[(size_t)NMAX * F2];   // h1@W2           (12.8 MB)

// ---------------- small kernels -------------------------------------------
__global__ void k_deg(const int* __restrict__ src, const int* __restrict__ dst, int E) {
    int e = blockIdx.x * blockDim.x + threadIdx.x;
    if (e < E) {
        atomicAdd(&g_deg_out[src[e]], 1);
        atomicAdd(&g_deg_in [dst[e]], 1);
    }
}

__global__ void k_norm(int n) {
    int i = blockIdx.x * blockDim.x + threadIdx.x;
    if (i < n) {
        int o = g_deg_out[i], d = g_deg_in[i];
        g_nsrc[i] = (o > 0) ? rsqrtf((float)o) : 1.0f;
        g_ndst[i] = (d > 0) ? rsqrtf((float)d) : 1.0f;
    }
}

// ---------------- row-scaled SGEMM:  C[M,N] = (A ⊙ rs) @ B ----------------
template<int BM, int BN, int BK, int TM, int TN>
__global__ void sgemm_rs(const float* __restrict__ A, const float* __restrict__ B,
                         const float* __restrict__ rs, float* __restrict__ C,
                         int M, int K, int N) {
    constexpr int NT = (BM / TM) * (BN / TN);
    __shared__ float As[BK][BM];
    __shared__ float Bs[BK][BN];

    const int tid  = threadIdx.x;
    const int bm   = blockIdx.x * BM;
    const int bn   = blockIdx.y * BN;
    const int tcol = tid % (BN / TN);
    const int trow = tid / (BN / TN);

    float acc[TM][TN];
#pragma unroll
    for (int i = 0; i < TM; i++)
#pragma unroll
        for (int j = 0; j < TN; j++) acc[i][j] = 0.0f;

    for (int k0 = 0; k0 < K; k0 += BK) {
        // load A tile (scaled by rs[row]); zero-pad rows >= M
#pragma unroll
        for (int idx = tid; idx < BM * BK; idx += NT) {
            int m = idx / BK, k = idx % BK;
            int gm = bm + m;
            float v = 0.0f;
            if (gm < M) v = A[(size_t)gm * K + k0 + k] * __ldg(&rs[gm]);
            As[k][m] = v;
        }
        // load B tile
#pragma unroll
        for (int idx = tid; idx < BK * BN; idx += NT) {
            int k = idx / BN, n = idx % BN;
            Bs[k][n] = B[(size_t)(k0 + k) * N + bn + n];
        }
        __syncthreads();

#pragma unroll
        for (int k = 0; k < BK; k++) {
            float ra[TM], rb[TN];
#pragma unroll
            for (int i = 0; i < TM; i++) ra[i] = As[k][trow * TM + i];
#pragma unroll
            for (int j = 0; j < TN; j++) rb[j] = Bs[k][tcol * TN + j];
#pragma unroll
            for (int i = 0; i < TM; i++)
#pragma unroll
                for (int j = 0; j < TN; j++) acc[i][j] = fmaf(ra[i], rb[j], acc[i][j]);
        }
        __syncthreads();
    }

#pragma unroll
    for (int i = 0; i < TM; i++) {
        int gm = bm + trow * TM + i;
        if (gm < M) {
#pragma unroll
            for (int j = 0; j < TN; j++) {
                int gn = bn + tcol * TN + j;
                C[(size_t)gm * N + gn] = acc[i][j];
            }
        }
    }
}

// ---------------- edge scatter-add: AGG[dst] += H[src], F floats/edge ------
// LOGF4: log2(F/4); each thread handles one float4 of one edge.
template<int LOGF4>
__global__ void k_scatter(const float* __restrict__ H,
                          const int* __restrict__ src, const int* __restrict__ dst,
                          float* __restrict__ AGG, int E) {
    constexpr int F = (1 << LOGF4) * 4;
    long idx = (long)blockIdx.x * blockDim.x + threadIdx.x;
    long total = (long)E << LOGF4;
    if (idx >= total) return;
    int e  = (int)(idx >> LOGF4);
    int f4 = (int)(idx & ((1 << LOGF4) - 1));
    int s = __ldg(&src[e]);
    int d = __ldg(&dst[e]);
    float4 v = *reinterpret_cast<const float4*>(H + (size_t)s * F + f4 * 4);
    float* out = AGG + (size_t)d * F + f4 * 4;
    atomicAdd(out + 0, v.x);
    atomicAdd(out + 1, v.y);
    atomicAdd(out + 2, v.z);
    atomicAdd(out + 3, v.w);
}

// ---------------- epilogues -----------------------------------------------
__global__ void k_epi1(const float* __restrict__ b1, int total) {  // relu(agg*ndst + b)
    int i = blockIdx.x * blockDim.x + threadIdx.x;
    if (i < total) {
        int row = i >> 8;               // F1 = 256
        float v = g_A1[i] * g_ndst[row] + __ldg(&b1[i & (F1 - 1)]);
        g_A1[i] = v > 0.0f ? v : 0.0f;
    }
}

__global__ void k_epi2(float* __restrict__ out, const float* __restrict__ b2, int total) {
    int i = blockIdx.x * blockDim.x + threadIdx.x;
    if (i < total) {
        int row = i >> 6;               // F2 = 64
        out[i] = out[i] * g_ndst[row] + __ldg(&b2[i & (F2 - 1)]);
    }
}

// ---------------- launch ---------------------------------------------------
extern "C" void kernel_launch(void* const* d_in, const int* in_sizes, int n_in,
                              void* d_out, int out_size) {
    const float* feat = (const float*)d_in[0];
    const int*   src  = (const int*)  d_in[1];
    const int*   dst  = (const int*)  d_in[2];
    const float* W1   = (const float*)d_in[3];
    const float* b1   = (const float*)d_in[4];
    const float* W2   = (const float*)d_in[5];
    const float* b2   = (const float*)d_in[6];
    float* out = (float*)d_out;

    const int N = in_sizes[0] / K1;   // 50000
    const int E = in_sizes[1];        // 800000

    void *p_dego, *p_degi, *p_nsrc, *p_ndst, *p_H1, *p_A1, *p_H2;
    cudaGetSymbolAddress(&p_dego, g_deg_out);
    cudaGetSymbolAddress(&p_degi, g_deg_in);
    cudaGetSymbolAddress(&p_nsrc, g_nsrc);
    cudaGetSymbolAddress(&p_ndst, g_ndst);
    cudaGetSymbolAddress(&p_H1,   g_H1);
    cudaGetSymbolAddress(&p_A1,   g_A1);
    cudaGetSymbolAddress(&p_H2,   g_H2);

    const int T = 256;

    // 1) degrees + norms
    cudaMemsetAsync(p_dego, 0, (size_t)N * sizeof(int));
    cudaMemsetAsync(p_degi, 0, (size_t)N * sizeof(int));
    k_deg <<<(E + T - 1) / T, T>>>(src, dst, E);
    k_norm<<<(N + T - 1) / T, T>>>(N);

    // 2) GEMM1: H1 = (feat ⊙ nsrc) @ W1   [N,512]x[512,256]
    {
        dim3 grid((N + 127) / 128, F1 / 128);
        sgemm_rs<128, 128, 8, 8, 8><<<grid, 256>>>(
            feat, W1, (const float*)p_nsrc, (float*)p_H1, N, K1, F1);
    }

    // 3) scatter layer 1 into A1
    cudaMemsetAsync(p_A1, 0, (size_t)N * F1 * sizeof(float));
    {
        long total = (long)E * (F1 / 4);
        k_scatter<6><<<(unsigned)((total + T - 1) / T), T>>>(
            (const float*)p_H1, src, dst, (float*)p_A1, E);
    }

    // 4) epilogue 1: h1 = relu(A1*ndst + b1)  (in place)
    k_epi1<<<(N * F1 + T - 1) / T, T>>>(b1, N * F1);

    // 5) GEMM2: H2 = (h1 ⊙ nsrc) @ W2   [N,256]x[256,64]
    {
        dim3 grid((N + 127) / 128, F2 / 64);
        sgemm_rs<128, 64, 8, 8, 4><<<grid, 256>>>(
            (const float*)p_A1, W2, (const float*)p_nsrc, (float*)p_H2, N, F1, F2);
    }

    // 6) scatter layer 2 into d_out
    cudaMemsetAsync(out, 0, (size_t)N * F2 * sizeof(float));
    {
        long total = (long)E * (F2 / 4);
        k_scatter<4><<<(unsigned)((total + T - 1) / T), T>>>(
            (const float*)p_H2, src, dst, out, E);
    }

    // 7) epilogue 2: out = out*ndst + b2
    k_epi2<<<(N * F2 + T - 1) / T, T>>>(out, b2, N * F2);
}

// round 3
// speedup vs baseline: 2.3838x; 2.3838x over previous
#include <cuda_runtime.h>
#include <math.h>

#define NMAX   50000
#define EMAX   800000
#define K1     512
#define F1     256
#define F2     64

// ---------------- scratch (static device globals) --------------------------
__device__ int   g_deg_out[NMAX];
__device__ int   g_deg_in [NMAX];
__device__ int   g_cursor [NMAX];
__device__ int   g_row_start[NMAX + 1];
__device__ int   g_esrc[EMAX];
__device__ float g_nsrc[NMAX];
__device__ float g_ndst[NMAX];
__device__ float g_H1[(size_t)NMAX * F1];   // X@W1
__device__ float g_A1[(size_t)NMAX * F1];   // relu(agg1)  (GEMM2 input)
__device__ float g_H2[(size_t)NMAX * F2];   // h1@W2

// ---------------- degrees / norms ------------------------------------------
__global__ void k_deg(const int* __restrict__ src, const int* __restrict__ dst, int E) {
    int e = blockIdx.x * blockDim.x + threadIdx.x;
    if (e < E) {
        atomicAdd(&g_deg_out[src[e]], 1);
        atomicAdd(&g_deg_in [dst[e]], 1);
    }
}

__global__ void k_norm(int n) {
    int i = blockIdx.x * blockDim.x + threadIdx.x;
    if (i < n) {
        int o = g_deg_out[i], d = g_deg_in[i];
        g_nsrc[i] = (o > 0) ? rsqrtf((float)o) : 1.0f;
        g_ndst[i] = (d > 0) ? rsqrtf((float)d) : 1.0f;
    }
}

// ---------------- exclusive scan of deg_in -> row_start (single block) -----
__device__ __forceinline__ int warp_incl_scan(int v) {
#pragma unroll
    for (int off = 1; off < 32; off <<= 1) {
        int t = __shfl_up_sync(0xFFFFFFFFu, v, off);
        if ((threadIdx.x & 31) >= off) v += t;
    }
    return v;
}

__global__ void k_scan(int n) {
    __shared__ int wsum[32];
    __shared__ int carry_s;
    if (threadIdx.x == 0) { g_row_start[0] = 0; carry_s = 0; }
    __syncthreads();
    for (int base = 0; base < n; base += 1024) {
        int i = base + threadIdx.x;
        int v = (i < n) ? g_deg_in[i] : 0;
        int s = warp_incl_scan(v);
        int wid = threadIdx.x >> 5, lid = threadIdx.x & 31;
        if (lid == 31) wsum[wid] = s;
        __syncthreads();
        if (wid == 0) wsum[lid] = warp_incl_scan(wsum[lid]);
        __syncthreads();
        int incl = s + (wid > 0 ? wsum[wid - 1] : 0) + carry_s;
        if (i < n) g_row_start[i + 1] = incl;
        __syncthreads();                 // everyone read carry_s
        if (threadIdx.x == 1023) carry_s = incl;
        __syncthreads();
    }
}

// ---------------- bucket edges by dst --------------------------------------
__global__ void k_fill(const int* __restrict__ src, const int* __restrict__ dst, int E) {
    int e = blockIdx.x * blockDim.x + threadIdx.x;
    if (e < E) {
        int d = dst[e];
        int pos = g_row_start[d] + atomicAdd(&g_cursor[d], 1);
        g_esrc[pos] = src[e];
    }
}

// ---------------- CSR gather-reduce + fused epilogue ------------------------
// F floats per node; L = F/4 lanes per node (float4 each); 256/L nodes per block.
template<int F, bool RELU>
__global__ void k_agg(const float* __restrict__ H, const float* __restrict__ bias,
                      float* __restrict__ out, int N) {
    constexpr int L   = F / 4;
    constexpr int GPB = 256 / L;
    int node = blockIdx.x * GPB + threadIdx.x / L;
    int lane = threadIdx.x % L;
    if (node >= N) return;

    int beg = g_row_start[node];
    int end = g_row_start[node + 1];

    const float4* Hv = (const float4*)H;
    float4 a0 = make_float4(0.f, 0.f, 0.f, 0.f);
    float4 a1 = make_float4(0.f, 0.f, 0.f, 0.f);

    int i = beg;
    for (; i + 1 < end; i += 2) {                 // 2-way MLP
        int s0 = __ldg(&g_esrc[i]);
        int s1 = __ldg(&g_esrc[i + 1]);
        float4 v0 = __ldg(&Hv[(size_t)s0 * L + lane]);
        float4 v1 = __ldg(&Hv[(size_t)s1 * L + lane]);
        a0.x += v0.x; a0.y += v0.y; a0.z += v0.z; a0.w += v0.w;
        a1.x += v1.x; a1.y += v1.y; a1.z += v1.z; a1.w += v1.w;
    }
    if (i < end) {
        int s0 = __ldg(&g_esrc[i]);
        float4 v0 = __ldg(&Hv[(size_t)s0 * L + lane]);
        a0.x += v0.x; a0.y += v0.y; a0.z += v0.z; a0.w += v0.w;
    }
    a0.x += a1.x; a0.y += a1.y; a0.z += a1.z; a0.w += a1.w;

    float nd = g_ndst[node];
    float4 b = __ldg(&((const float4*)bias)[lane]);
    float4 r;
    r.x = a0.x * nd + b.x; r.y = a0.y * nd + b.y;
    r.z = a0.z * nd + b.z; r.w = a0.w * nd + b.w;
    if (RELU) {
        r.x = fmaxf(r.x, 0.f); r.y = fmaxf(r.y, 0.f);
        r.z = fmaxf(r.z, 0.f); r.w = fmaxf(r.w, 0.f);
    }
    ((float4*)out)[(size_t)node * L + lane] = r;
}

// ---------------- row-scaled SGEMM:  C = (A ⊙ rs) @ B ----------------------
template<int BM, int BN, int BK, int TM, int TN>
__global__ void sgemm_rs(const float* __restrict__ A, const float* __restrict__ B,
                         const float* __restrict__ rs, float* __restrict__ C,
                         int M, int K, int N) {
    constexpr int NT  = (BM / TM) * (BN / TN);
    constexpr int ASS = BM + 4;                  // pad: keeps float4-aligned rows
    __shared__ float As[BK][ASS];
    __shared__ float Bs[BK][BN];

    const int tid  = threadIdx.x;
    const int bm   = blockIdx.x * BM;
    const int bn   = blockIdx.y * BN;
    const int tcol = tid % (BN / TN);
    const int trow = tid / (BN / TN);

    float acc[TM][TN];
#pragma unroll
    for (int i = 0; i < TM; i++)
#pragma unroll
        for (int j = 0; j < TN; j++) acc[i][j] = 0.0f;

    constexpr int AF4 = BM * BK / 4;
    constexpr int BF4 = BK * BN / 4;

    for (int k0 = 0; k0 < K; k0 += BK) {
#pragma unroll
        for (int idx = tid; idx < AF4; idx += NT) {
            int m  = idx / (BK / 4);
            int kk = (idx % (BK / 4)) * 4;
            int gm = bm + m;
            float4 v = make_float4(0.f, 0.f, 0.f, 0.f);
            if (gm < M) {
                v = *(const float4*)(A + (size_t)gm * K + k0 + kk);
                float s = __ldg(&rs[gm]);
                v.x *= s; v.y *= s; v.z *= s; v.w *= s;
            }
            As[kk + 0][m] = v.x; As[kk + 1][m] = v.y;
            As[kk + 2][m] = v.z; As[kk + 3][m] = v.w;
        }
#pragma unroll
        for (int idx = tid; idx < BF4; idx += NT) {
            int k  = idx / (BN / 4);
            int n4 = idx % (BN / 4);
            *(float4*)&Bs[k][n4 * 4] =
                *(const float4*)(B + (size_t)(k0 + k) * N + bn + n4 * 4);
        }
        __syncthreads();

#pragma unroll
        for (int k = 0; k < BK; k++) {
            float ra[TM], rb[TN];
#pragma unroll
            for (int i = 0; i < TM; i += 4) {
                float4 t = *(const float4*)&As[k][trow * TM + i];
                ra[i] = t.x; ra[i + 1] = t.y; ra[i + 2] = t.z; ra[i + 3] = t.w;
            }
#pragma unroll
            for (int j = 0; j < TN; j += 4) {
                float4 t = *(const float4*)&Bs[k][tcol * TN + j];
                rb[j] = t.x; rb[j + 1] = t.y; rb[j + 2] = t.z; rb[j + 3] = t.w;
            }
#pragma unroll
            for (int i = 0; i < TM; i++)
#pragma unroll
                for (int j = 0; j < TN; j++)
                    acc[i][j] = fmaf(ra[i], rb[j], acc[i][j]);
        }
        __syncthreads();
    }

#pragma unroll
    for (int i = 0; i < TM; i++) {
        int gm = bm + trow * TM + i;
        if (gm < M) {
#pragma unroll
            for (int j = 0; j < TN; j += 4) {
                float4 t = make_float4(acc[i][j], acc[i][j + 1], acc[i][j + 2], acc[i][j + 3]);
                *(float4*)(C + (size_t)gm * N + bn + tcol * TN + j) = t;
            }
        }
    }
}

// ---------------- launch ----------------------------------------------------
extern "C" void kernel_launch(void* const* d_in, const int* in_sizes, int n_in,
                              void* d_out, int out_size) {
    const float* feat = (const float*)d_in[0];
    const int*   src  = (const int*)  d_in[1];
    const int*   dst  = (const int*)  d_in[2];
    const float* W1   = (const float*)d_in[3];
    const float* b1   = (const float*)d_in[4];
    const float* W2   = (const float*)d_in[5];
    const float* b2   = (const float*)d_in[6];
    float* out = (float*)d_out;

    const int N = in_sizes[0] / K1;   // 50000
    const int E = in_sizes[1];        // 800000

    void *p_dego, *p_degi, *p_cur, *p_nsrc, *p_H1, *p_A1, *p_H2;
    cudaGetSymbolAddress(&p_dego, g_deg_out);
    cudaGetSymbolAddress(&p_degi, g_deg_in);
    cudaGetSymbolAddress(&p_cur,  g_cursor);
    cudaGetSymbolAddress(&p_nsrc, g_nsrc);
    cudaGetSymbolAddress(&p_H1,   g_H1);
    cudaGetSymbolAddress(&p_A1,   g_A1);
    cudaGetSymbolAddress(&p_H2,   g_H2);

    const int T = 256;

    // 1) degrees + norms + CSR build
    cudaMemsetAsync(p_dego, 0, (size_t)N * sizeof(int));
    cudaMemsetAsync(p_degi, 0, (size_t)N * sizeof(int));
    cudaMemsetAsync(p_cur,  0, (size_t)N * sizeof(int));
    k_deg  <<<(E + T - 1) / T, T>>>(src, dst, E);
    k_norm <<<(N + T - 1) / T, T>>>(N);
    k_scan <<<1, 1024>>>(N);
    k_fill <<<(E + T - 1) / T, T>>>(src, dst, E);

    // 2) GEMM1: H1 = (feat ⊙ nsrc) @ W1
    {
        dim3 grid((N + 127) / 128, F1 / 128);
        sgemm_rs<128, 128, 16, 8, 8><<<grid, 256>>>(
            feat, W1, (const float*)p_nsrc, (float*)p_H1, N, K1, F1);
    }

    // 3) aggregate layer 1 (CSR gather-reduce, fused ndst+bias+relu)
    {
        constexpr int GPB = 256 / (F1 / 4);   // 4 nodes per block
        k_agg<F1, true><<<(N + GPB - 1) / GPB, 256>>>(
            (const float*)p_H1, b1, (float*)p_A1, N);
    }

    // 4) GEMM2: H2 = (h1 ⊙ nsrc) @ W2
    {
        dim3 grid((N + 127) / 128, 1);
        sgemm_rs<128, 64, 16, 8, 4><<<grid, 256>>>(
            (const float*)p_A1, W2, (const float*)p_nsrc, (float*)p_H2, N, F1, F2);
    }

    // 5) aggregate layer 2 (fused ndst+bias), writes d_out directly
    {
        constexpr int GPB = 256 / (F2 / 4);   // 16 nodes per block
        k_agg<F2, false><<<(N + GPB - 1) / GPB, 256>>>(
            (const float*)p_H2, b2, out, N);
    }
}